// round 16
// baseline (speedup 1.0000x reference)
#include <cuda_runtime.h>
#include <cuda_fp16.h>
#include <math.h>
#include <stdint.h>

#define DIM    1024
#define MLPD   4096
#define DSTATE 16
#define DCONV  4
#define HALF   1024
#define DINNER 2048
#define DTRANK 64
#define BSZ    2
#define SEQ    2048
#define NTOK   (BSZ * SEQ)   // 4096
#define LN_EPS 1e-5f
#define NPERSIST 296          // 148 SMs * 2 CTAs

// ---------------- scratch (device globals) ----------------------------------
__device__ float g_xdbl[NTOK * 96];
__device__ float g_delta[NTOK * HALF];
__device__ float g_res1[NTOK * DIM];

__device__ __half h_ln1[NTOK * DIM];
__device__ __half h_xz[NTOK * DINNER];
__device__ __half h_u[NTOK * HALF];
__device__ __half h_xdbl[NTOK * 96];
__device__ __half h_y[NTOK * DINNER];
__device__ __half h_ln2[NTOK * DIM];
__device__ __half h_mlp[NTOK * MLPD];

__device__ __half w16_in[DINNER * DIM];
__device__ __half w16_xp[96 * HALF];
__device__ __half w16_dt[HALF * DTRANK];
__device__ __half w16_out[DIM * DINNER];
__device__ __half w16_m1[MLPD * DIM];
__device__ __half w16_m2[DIM * MLPD];

// ======================= helpers ============================================
__device__ __forceinline__ uint32_t smem_u32(const void* p) {
    uint32_t a;
    asm("{ .reg .u64 t; cvta.to.shared.u64 t, %1; cvt.u32.u64 %0, t; }"
        : "=r"(a) : "l"(p));
    return a;
}
__device__ __forceinline__ void cp16(uint32_t dst, const void* src) {
    asm volatile("cp.async.cg.shared.global [%0], [%1], 16;"
                 :: "r"(dst), "l"(src) : "memory");
}
__device__ __forceinline__ void cp16z(uint32_t dst, const void* src, int sz) {
    asm volatile("cp.async.cg.shared.global [%0], [%1], 16, %2;"
                 :: "r"(dst), "l"(src), "r"(sz) : "memory");
}
#define CP_COMMIT() asm volatile("cp.async.commit_group;" ::: "memory")
#define CP_WAIT2()  asm volatile("cp.async.wait_group 2;" ::: "memory")

__device__ __forceinline__ void lm4(uint32_t& r0, uint32_t& r1, uint32_t& r2,
                                    uint32_t& r3, uint32_t addr) {
    asm volatile("ldmatrix.sync.aligned.m8n8.x4.shared.b16 {%0,%1,%2,%3}, [%4];"
                 : "=r"(r0), "=r"(r1), "=r"(r2), "=r"(r3) : "r"(addr));
}
__device__ __forceinline__ void mma_f16(float* c, const uint32_t* a, const uint32_t* b) {
    asm volatile(
        "mma.sync.aligned.m16n8k16.row.col.f32.f16.f16.f32 "
        "{%0,%1,%2,%3}, {%4,%5,%6,%7}, {%8,%9}, {%0,%1,%2,%3};"
        : "+f"(c[0]), "+f"(c[1]), "+f"(c[2]), "+f"(c[3])
        : "r"(a[0]), "r"(a[1]), "r"(a[2]), "r"(a[3]), "r"(b[0]), "r"(b[1]));
}

// ======================= fp16 MMA GEMM (persistent tiles, 256 thr) ==========
// C[M,N] = A[M,K](lda) * B[N,K]^T(ldb). 128x128 CTA tile, 8 warps (64x32 each).
// MODE 0: none  1: softplus(+bias)  2: +resid  3: gelu(+bias)  4: +bias+resid
#define PITCH_H 72                              // halfs per 64-half row (+8 pad)
#define STG_BYTES (2 * 128 * PITCH_H * 2)       // 36864
#define GEMM_SMEM (3 * STG_BYTES)               // 110592

template<int MODE, bool W32, bool W16>
__global__ __launch_bounds__(256, 2) void gemm_h(
    const __half* __restrict__ A, const __half* __restrict__ B,
    float* __restrict__ C, __half* __restrict__ C16,
    int N, int K, int lda, int ldb, int ntx, int ntiles,
    const float* __restrict__ bias, const float* __restrict__ resid)
{
    extern __shared__ char smraw[];
    const int tid = threadIdx.x;
    const int wid = tid >> 5, lane = tid & 31;
    const int gid = lane >> 2, t4 = lane & 3;
    const int wm = (wid >> 2) * 64, wn = (wid & 3) * 32;
    const int NC = K >> 6;                      // K chunks of 64
    uint32_t sbase = smem_u32(smraw);

    const uint32_t aoff = (uint32_t)((wm + (lane & 15)) * PITCH_H + ((lane >> 4) << 3)) * 2;
    const uint32_t boff = 128 * PITCH_H * 2 +
        (uint32_t)((wn + ((lane >> 4) << 3) + (lane & 7)) * PITCH_H + (((lane >> 3) & 1) << 3)) * 2;

    for (int tile = blockIdx.x; tile < ntiles; tile += gridDim.x) {
        const int row0 = (tile / ntx) * 128, col0 = (tile % ntx) * 128;

        auto load_chunk = [&](int c, int s) {
            uint32_t As = sbase + (uint32_t)s * STG_BYTES;
            uint32_t Bs = As + 128 * PITCH_H * 2;
            int k0 = c * 64;
            #pragma unroll
            for (int i = 0; i < 4; i++) {
                int idx = tid + 256 * i;
                int r = idx >> 3, c8 = (idx & 7) * 8;
                cp16(As + (uint32_t)(r * PITCH_H + c8) * 2,
                     A + (size_t)(row0 + r) * lda + k0 + c8);
            }
            #pragma unroll
            for (int i = 0; i < 4; i++) {
                int idx = tid + 256 * i;
                int r = idx >> 3, c8 = (idx & 7) * 8;
                int brow = col0 + r;
                const __half* src = B + (size_t)(brow < N ? brow : 0) * ldb + k0 + c8;
                cp16z(Bs + (uint32_t)(r * PITCH_H + c8) * 2, src, brow < N ? 16 : 0);
            }
        };

        float acc[4][4][4];
        #pragma unroll
        for (int i = 0; i < 4; i++)
            #pragma unroll
            for (int j = 0; j < 4; j++)
                #pragma unroll
                for (int q = 0; q < 4; q++) acc[i][j][q] = 0.f;

        #pragma unroll
        for (int c = 0; c < 2; c++) {
            if (c < NC) load_chunk(c, c);
            CP_COMMIT();
        }

        for (int c = 0; c < NC; c++) {
            if (c + 2 < NC) load_chunk(c + 2, (c + 2) % 3);
            CP_COMMIT();
            CP_WAIT2();
            __syncthreads();

            uint32_t stage = sbase + (uint32_t)(c % 3) * STG_BYTES;
            #pragma unroll
            for (int k16 = 0; k16 < 4; k16++) {
                uint32_t kb = (uint32_t)(k16 * 16) * 2;
                uint32_t af[4][4], bf[4][2];
                #pragma unroll
                for (int mt = 0; mt < 4; mt++)
                    lm4(af[mt][0], af[mt][1], af[mt][2], af[mt][3],
                        stage + aoff + kb + (uint32_t)(mt * 16 * PITCH_H) * 2);
                #pragma unroll
                for (int np = 0; np < 2; np++)
                    lm4(bf[2*np][0], bf[2*np][1], bf[2*np+1][0], bf[2*np+1][1],
                        stage + boff + kb + (uint32_t)(np * 16 * PITCH_H) * 2);
                #pragma unroll
                for (int mt = 0; mt < 4; mt++)
                    #pragma unroll
                    for (int nt = 0; nt < 4; nt++)
                        mma_f16(acc[mt][nt], af[mt], bf[nt]);
            }
            __syncthreads();
        }

        // ---- epilogue --------------------------------------------------
        #pragma unroll
        for (int mt = 0; mt < 4; mt++) {
            #pragma unroll
            for (int r2 = 0; r2 < 2; r2++) {
                int m = row0 + wm + mt * 16 + gid + r2 * 8;
                #pragma unroll
                for (int nt = 0; nt < 4; nt++) {
                    int n = col0 + wn + nt * 8 + 2 * t4;
                    if (n < N) {
                        float v0 = acc[mt][nt][r2 * 2];
                        float v1 = acc[mt][nt][r2 * 2 + 1];
                        if (MODE == 1 || MODE == 3 || MODE == 4) {
                            v0 += bias[n]; v1 += bias[n + 1];
                        }
                        if (MODE == 1) {
                            v0 = (v0 > 20.f) ? v0 : log1pf(expf(v0));
                            v1 = (v1 > 20.f) ? v1 : log1pf(expf(v1));
                        }
                        if (MODE == 3) {
                            const float kq = 0.70710678118654752f;
                            v0 = 0.5f * v0 * (1.f + erff(v0 * kq));
                            v1 = 0.5f * v1 * (1.f + erff(v1 * kq));
                        }
                        if (MODE == 2 || MODE == 4) {
                            const float* rp = resid + (size_t)m * N + n;
                            v0 += rp[0]; v1 += rp[1];
                        }
                        if (W32)
                            *(float2*)(C + (size_t)m * N + n) = make_float2(v0, v1);
                        if (W16)
                            *(__half2*)(C16 + (size_t)m * N + n) = __floats2half2_rn(v0, v1);
                    }
                }
            }
        }
    }
}

// ======================= weight conversion ==================================
struct CvtArgs {
    const float* src[6];
    __half* dst[6];
    int off[7];
};
__global__ __launch_bounds__(256) void cvt_kernel(CvtArgs a) {
    int i = blockIdx.x * blockDim.x + threadIdx.x;
    if (i >= a.off[6]) return;
    int s = 0;
    #pragma unroll
    for (int k = 1; k < 6; k++) if (i >= a.off[k]) s = k;
    int j = i - a.off[s];
    float4 v = ((const float4*)a.src[s])[j];
    __half2* d = (__half2*)a.dst[s];
    d[2 * j]     = __floats2half2_rn(v.x, v.y);
    d[2 * j + 1] = __floats2half2_rn(v.z, v.w);
}

// ======================= LayerNorm (f16 out) ================================
__global__ __launch_bounds__(256) void ln_kernel(
    const float* __restrict__ in, __half* __restrict__ out,
    const float* __restrict__ g, const float* __restrict__ b)
{
    int row = blockIdx.x;
    const float* x = in + (size_t)row * DIM;
    float4 v = *(const float4*)(x + threadIdx.x * 4);
    float s  = v.x + v.y + v.z + v.w;
    float sq = v.x*v.x + v.y*v.y + v.z*v.z + v.w*v.w;
    #pragma unroll
    for (int o = 16; o; o >>= 1) {
        s  += __shfl_xor_sync(0xffffffffu, s,  o);
        sq += __shfl_xor_sync(0xffffffffu, sq, o);
    }
    __shared__ float ss[8], sqq[8];
    int w = threadIdx.x >> 5;
    if ((threadIdx.x & 31) == 0) { ss[w] = s; sqq[w] = sq; }
    __syncthreads();
    s = 0.f; sq = 0.f;
    #pragma unroll
    for (int i = 0; i < 8; i++) { s += ss[i]; sq += sqq[i]; }
    float mu = s * (1.0f / DIM);
    float var = sq * (1.0f / DIM) - mu * mu;
    float rs = rsqrtf(var + LN_EPS);
    float4 gg = *(const float4*)(g + threadIdx.x * 4);
    float4 bb = *(const float4*)(b + threadIdx.x * 4);
    __half2 p0 = __floats2half2_rn((v.x - mu) * rs * gg.x + bb.x,
                                   (v.y - mu) * rs * gg.y + bb.y);
    __half2 p1 = __floats2half2_rn((v.z - mu) * rs * gg.z + bb.z,
                                   (v.w - mu) * rs * gg.w + bb.w);
    __half2* o2 = (__half2*)(out + (size_t)row * DIM);
    o2[threadIdx.x * 2] = p0;
    o2[threadIdx.x * 2 + 1] = p1;
}

// ---------------- depthwise conv + SiLU (vectorized: 2 channels/thread) -----
__device__ __forceinline__ float silu(float v) { return v / (1.0f + __expf(-v)); }

__global__ __launch_bounds__(256) void conv_silu_kernel(
    const __half* __restrict__ xz,
    const float* __restrict__ wx, const float* __restrict__ bx,
    const float* __restrict__ wz, const float* __restrict__ bz,
    __half* __restrict__ u16, __half* __restrict__ y16)
{
    int idx = blockIdx.x * blockDim.x + threadIdx.x;   // NTOK*HALF/2 threads
    int d2 = idx & (HALF / 2 - 1);
    int d = d2 * 2;
    int token = idx >> 9;
    int b = token >> 11;
    int l = token & (SEQ - 1);

    float4 wxa = ((const float4*)wx)[d];
    float4 wxb = ((const float4*)wx)[d + 1];
    float4 wza = ((const float4*)wz)[d];
    float4 wzb = ((const float4*)wz)[d + 1];
    float ax0 = bx[d], ax1 = bx[d + 1];
    float az0 = bz[d], az1 = bz[d + 1];

    const __half* base = xz + (size_t)(b * SEQ) * DINNER + d;
    #pragma unroll
    for (int k = 0; k < DCONV; k++) {
        int lp = l - 1 + k;
        if (lp >= 0 && lp < SEQ) {
            float2 xv = __half22float2(*(const __half2*)(base + (size_t)lp * DINNER));
            float2 zv = __half22float2(*(const __half2*)(base + (size_t)lp * DINNER + HALF));
            float wxk0 = (&wxa.x)[k], wxk1 = (&wxb.x)[k];
            float wzk0 = (&wza.x)[k], wzk1 = (&wzb.x)[k];
            ax0 += xv.x * wxk0; ax1 += xv.y * wxk1;
            az0 += zv.x * wzk0; az1 += zv.y * wzk1;
        }
    }
    *(__half2*)(u16 + (size_t)token * HALF + d) =
        __floats2half2_rn(silu(ax0), silu(ax1));
    *(__half2*)(y16 + (size_t)token * DINNER + HALF + d) =
        __floats2half2_rn(silu(az0), silu(az1));
}

// ---------------- selective scan: 4 lanes/channel, 4 states/lane ------------
// Warp = 8 channels. B/C loaded as float4. 2-level shfl tree within 4 lanes.
__global__ __launch_bounds__(32) void scan_kernel(
    const float* __restrict__ delta, const __half* __restrict__ u,
    const float* __restrict__ xdbl, const float* __restrict__ A_log,
    const float* __restrict__ Dp, __half* __restrict__ y)
{
    int gt = blockIdx.x * 32 + threadIdx.x;   // BSZ*HALF*4 threads
    int c = gt >> 2;                           // channel 0..2047
    int ln = gt & 3;                           // 4 lanes per channel
    int b = c >> 10;
    int d = c & (HALF - 1);
    int n0 = ln * 4;                           // states n0..n0+3

    float4 al = *(const float4*)(A_log + d * DSTATE + n0);
    float a0 = -expf(al.x), a1 = -expf(al.y);
    float a2 = -expf(al.z), a3 = -expf(al.w);
    float Dd = Dp[d];
    float h0 = 0.f, h1 = 0.f, h2 = 0.f, h3 = 0.f;

    const float*  dptr = delta + (size_t)b * SEQ * HALF + d;
    const __half* uptr = u     + (size_t)b * SEQ * HALF + d;
    const float*  bptr = xdbl  + (size_t)b * SEQ * 96 + DTRANK + n0;
    const float*  cptr = xdbl  + (size_t)b * SEQ * 96 + DTRANK + DSTATE + n0;
    __half* yptr = y + (size_t)b * SEQ * DINNER + d;

    float dl[8], uv[8];
    float4 Bv[8], Cv[8];
    #pragma unroll
    for (int j = 0; j < 8; j++) {
        dl[j] = dptr[j * HALF]; uv[j] = __half2float(uptr[j * HALF]);
        Bv[j] = *(const float4*)(bptr + j * 96);
        Cv[j] = *(const float4*)(cptr + j * 96);
    }

    for (int t = 0; t < SEQ; t += 8) {
        float nd[8], nu[8];
        float4 nB[8], nC[8];
        #pragma unroll
        for (int j = 0; j < 8; j++) {
            int tp = t + 8 + j; tp = (tp < SEQ) ? tp : SEQ - 1;
            nd[j] = dptr[tp * HALF]; nu[j] = __half2float(uptr[tp * HALF]);
            nB[j] = *(const float4*)(bptr + tp * 96);
            nC[j] = *(const float4*)(cptr + tp * 96);
        }

        float p[8];
        #pragma unroll
        for (int j = 0; j < 8; j++) {
            float e0 = __expf(dl[j] * a0);
            float e1 = __expf(dl[j] * a1);
            float e2 = __expf(dl[j] * a2);
            float e3 = __expf(dl[j] * a3);
            float du = dl[j] * uv[j];
            h0 = e0 * h0 + du * Bv[j].x;
            h1 = e1 * h1 + du * Bv[j].y;
            h2 = e2 * h2 + du * Bv[j].z;
            h3 = e3 * h3 + du * Bv[j].w;
            p[j] = (h0 * Cv[j].x + h1 * Cv[j].y) + (h2 * Cv[j].z + h3 * Cv[j].w);
        }

        // 2-level tree within each 4-lane group (8 interleaved chains)
        #pragma unroll
        for (int o = 2; o; o >>= 1) {
            #pragma unroll
            for (int j = 0; j < 8; j++)
                p[j] += __shfl_xor_sync(0xffffffffu, p[j], o);
        }

        if (ln == 0) {
            #pragma unroll
            for (int j = 0; j < 8; j++)
                yptr[(size_t)(t + j) * DINNER] = __float2half(p[j] + uv[j] * Dd);
        }
        #pragma unroll
        for (int j = 0; j < 8; j++) {
            dl[j] = nd[j]; uv[j] = nu[j]; Bv[j] = nB[j]; Cv[j] = nC[j];
        }
    }
}

// ======================= launch =============================================
static inline int pgrid(int ntiles) { return ntiles < NPERSIST ? ntiles : NPERSIST; }

extern "C" void kernel_launch(void* const* d_in, const int* in_sizes, int n_in,
                              void* d_out, int out_size)
{
    const float* x         = (const float*)d_in[0];
    const float* ln1_g     = (const float*)d_in[1];
    const float* ln1_b     = (const float*)d_in[2];
    const float* in_proj_w = (const float*)d_in[3];
    const float* conv_x_w  = (const float*)d_in[4];
    const float* conv_x_b  = (const float*)d_in[5];
    const float* conv_z_w  = (const float*)d_in[6];
    const float* conv_z_b  = (const float*)d_in[7];
    const float* x_proj_w  = (const float*)d_in[8];
    const float* dt_proj_w = (const float*)d_in[9];
    const float* dt_proj_b = (const float*)d_in[10];
    const float* A_log     = (const float*)d_in[11];
    const float* Dp        = (const float*)d_in[12];
    const float* out_proj_w= (const float*)d_in[13];
    const float* ln2_g     = (const float*)d_in[14];
    const float* ln2_b     = (const float*)d_in[15];
    const float* mlp_w1    = (const float*)d_in[16];
    const float* mlp_b1    = (const float*)d_in[17];
    const float* mlp_w2    = (const float*)d_in[18];
    const float* mlp_b2    = (const float*)d_in[19];
    float* out = (float*)d_out;

    float *xdbl, *delta, *res1;
    cudaGetSymbolAddress((void**)&xdbl, g_xdbl);
    cudaGetSymbolAddress((void**)&delta,g_delta);
    cudaGetSymbolAddress((void**)&res1, g_res1);

    __half *hln1, *hxz, *hu, *hxdbl, *hy, *hln2, *hmlp;
    __half *win, *wxp, *wdt, *wout, *wm1, *wm2;
    cudaGetSymbolAddress((void**)&hln1, h_ln1);
    cudaGetSymbolAddress((void**)&hxz,  h_xz);
    cudaGetSymbolAddress((void**)&hu,   h_u);
    cudaGetSymbolAddress((void**)&hxdbl,h_xdbl);
    cudaGetSymbolAddress((void**)&hy,   h_y);
    cudaGetSymbolAddress((void**)&hln2, h_ln2);
    cudaGetSymbolAddress((void**)&hmlp, h_mlp);
    cudaGetSymbolAddress((void**)&win,  w16_in);
    cudaGetSymbolAddress((void**)&wxp,  w16_xp);
    cudaGetSymbolAddress((void**)&wdt,  w16_dt);
    cudaGetSymbolAddress((void**)&wout, w16_out);
    cudaGetSymbolAddress((void**)&wm1,  w16_m1);
    cudaGetSymbolAddress((void**)&wm2,  w16_m2);

    cudaFuncSetAttribute(gemm_h<0,false,true>, cudaFuncAttributeMaxDynamicSharedMemorySize, GEMM_SMEM);
    cudaFuncSetAttribute(gemm_h<0,true,true>,  cudaFuncAttributeMaxDynamicSharedMemorySize, GEMM_SMEM);
    cudaFuncSetAttribute(gemm_h<1,true,false>, cudaFuncAttributeMaxDynamicSharedMemorySize, GEMM_SMEM);
    cudaFuncSetAttribute(gemm_h<2,true,false>, cudaFuncAttributeMaxDynamicSharedMemorySize, GEMM_SMEM);
    cudaFuncSetAttribute(gemm_h<3,false,true>, cudaFuncAttributeMaxDynamicSharedMemorySize, GEMM_SMEM);
    cudaFuncSetAttribute(gemm_h<4,true,false>, cudaFuncAttributeMaxDynamicSharedMemorySize, GEMM_SMEM);

    // 0. convert weights to f16
    CvtArgs ca;
    ca.src[0] = in_proj_w;  ca.dst[0] = win;  int n0 = DINNER * DIM / 4;
    ca.src[1] = x_proj_w;   ca.dst[1] = wxp;  int n1 = 96 * HALF / 4;
    ca.src[2] = dt_proj_w;  ca.dst[2] = wdt;  int n2 = HALF * DTRANK / 4;
    ca.src[3] = out_proj_w; ca.dst[3] = wout; int n3 = DIM * DINNER / 4;
    ca.src[4] = mlp_w1;     ca.dst[4] = wm1;  int n4 = MLPD * DIM / 4;
    ca.src[5] = mlp_w2;     ca.dst[5] = wm2;  int n5 = DIM * MLPD / 4;
    ca.off[0] = 0;
    ca.off[1] = n0; ca.off[2] = n0+n1; ca.off[3] = n0+n1+n2;
    ca.off[4] = n0+n1+n2+n3; ca.off[5] = n0+n1+n2+n3+n4; ca.off[6] = n0+n1+n2+n3+n4+n5;
    cvt_kernel<<<(ca.off[6] + 255) / 256, 256>>>(ca);

    // 1. LN1 -> f16
    ln_kernel<<<NTOK, 256>>>(x, hln1, ln1_g, ln1_b);
    // 2. in_proj -> xz f16 (512 tiles)
    gemm_h<0,false,true><<<pgrid(512), 256, GEMM_SMEM>>>(
        hln1, win, nullptr, hxz, DINNER, DIM, DIM, DIM, 16, 512, nullptr, nullptr);
    // 3. conv + silu (2 channels/thread)
    conv_silu_kernel<<<(NTOK*HALF/2)/256, 256>>>(hxz, conv_x_w, conv_x_b,
                                                 conv_z_w, conv_z_b, hu, hy);
    // 4. x_proj (32 tiles)
    gemm_h<0,true,true><<<pgrid(32), 256, GEMM_SMEM>>>(
        hu, wxp, xdbl, hxdbl, 96, HALF, HALF, HALF, 1, 32, nullptr, nullptr);
    // 5. dt_proj + softplus -> delta f32 (256 tiles)
    gemm_h<1,true,false><<<pgrid(256), 256, GEMM_SMEM>>>(
        hxdbl, wdt, delta, nullptr, HALF, DTRANK, 96, DTRANK, 8, 256,
        dt_proj_b, nullptr);
    // 6. selective scan -> h_y left half (4 lanes/channel, 1-warp blocks)
    scan_kernel<<<(BSZ*HALF*4)/32, 32>>>(delta, hu, xdbl, A_log, Dp, hy);
    // 7. out_proj + residual (256 tiles)
    gemm_h<2,true,false><<<pgrid(256), 256, GEMM_SMEM>>>(
        hy, wout, res1, nullptr, DIM, DINNER, DINNER, DINNER, 8, 256,
        nullptr, x);
    // 8. LN2 -> f16
    ln_kernel<<<NTOK, 256>>>(res1, hln2, ln2_g, ln2_b);
    // 9. mlp1 + gelu -> f16 (1024 tiles)
    gemm_h<3,false,true><<<pgrid(1024), 256, GEMM_SMEM>>>(
        hln2, wm1, nullptr, hmlp, MLPD, DIM, DIM, DIM, 32, 1024,
        mlp_b1, nullptr);
    // 10. mlp2 + bias + residual -> out (256 tiles)
    gemm_h<4,true,false><<<pgrid(256), 256, GEMM_SMEM>>>(
        hmlp, wm2, out, nullptr, DIM, MLPD, MLPD, MLPD, 8, 256,
        mlp_b2, res1);
}

// round 17
// speedup vs baseline: 1.0484x; 1.0484x over previous
#include <cuda_runtime.h>
#include <cuda_fp16.h>
#include <math.h>
#include <stdint.h>

#define DIM    1024
#define MLPD   4096
#define DSTATE 16
#define DCONV  4
#define HALF   1024
#define DINNER 2048
#define DTRANK 64
#define BSZ    2
#define SEQ    2048
#define NTOK   (BSZ * SEQ)   // 4096
#define LN_EPS 1e-5f
#define NPERSIST 296          // 148 SMs * 2 CTAs

// ---------------- scratch (device globals) ----------------------------------
__device__ float g_xdbl[NTOK * 96];
__device__ float g_delta[NTOK * HALF];
__device__ float g_res1[NTOK * DIM];

__device__ __half h_ln1[NTOK * DIM];
__device__ __half h_xz[NTOK * DINNER];
__device__ __half h_u[NTOK * HALF];
__device__ __half h_xdbl[NTOK * 96];
__device__ __half h_y[NTOK * DINNER];
__device__ __half h_ln2[NTOK * DIM];
__device__ __half h_mlp[NTOK * MLPD];

__device__ __half w16_in[DINNER * DIM];
__device__ __half w16_xp[96 * HALF];
__device__ __half w16_dt[HALF * DTRANK];
__device__ __half w16_out[DIM * DINNER];
__device__ __half w16_m1[MLPD * DIM];
__device__ __half w16_m2[DIM * MLPD];

// ======================= helpers ============================================
__device__ __forceinline__ uint32_t smem_u32(const void* p) {
    uint32_t a;
    asm("{ .reg .u64 t; cvta.to.shared.u64 t, %1; cvt.u32.u64 %0, t; }"
        : "=r"(a) : "l"(p));
    return a;
}
__device__ __forceinline__ void cp16(uint32_t dst, const void* src) {
    asm volatile("cp.async.cg.shared.global [%0], [%1], 16;"
                 :: "r"(dst), "l"(src) : "memory");
}
__device__ __forceinline__ void cp16z(uint32_t dst, const void* src, int sz) {
    asm volatile("cp.async.cg.shared.global [%0], [%1], 16, %2;"
                 :: "r"(dst), "l"(src), "r"(sz) : "memory");
}
#define CP_COMMIT() asm volatile("cp.async.commit_group;" ::: "memory")
#define CP_WAIT2()  asm volatile("cp.async.wait_group 2;" ::: "memory")

__device__ __forceinline__ void lm4(uint32_t& r0, uint32_t& r1, uint32_t& r2,
                                    uint32_t& r3, uint32_t addr) {
    asm volatile("ldmatrix.sync.aligned.m8n8.x4.shared.b16 {%0,%1,%2,%3}, [%4];"
                 : "=r"(r0), "=r"(r1), "=r"(r2), "=r"(r3) : "r"(addr));
}
__device__ __forceinline__ void mma_f16(float* c, const uint32_t* a, const uint32_t* b) {
    asm volatile(
        "mma.sync.aligned.m16n8k16.row.col.f32.f16.f16.f32 "
        "{%0,%1,%2,%3}, {%4,%5,%6,%7}, {%8,%9}, {%0,%1,%2,%3};"
        : "+f"(c[0]), "+f"(c[1]), "+f"(c[2]), "+f"(c[3])
        : "r"(a[0]), "r"(a[1]), "r"(a[2]), "r"(a[3]), "r"(b[0]), "r"(b[1]));
}

// ======================= fp16 MMA GEMM (persistent tiles, 256 thr) ==========
// C[M,N] = A[M,K](lda) * B[N,K]^T(ldb). 128x128 CTA tile, 8 warps (64x32 each).
// MODE 0: none  1: softplus(+bias)  2: +resid  3: gelu(+bias)  4: +bias+resid
#define PITCH_H 72                              // halfs per 64-half row (+8 pad)
#define STG_BYTES (2 * 128 * PITCH_H * 2)       // 36864
#define GEMM_SMEM (3 * STG_BYTES)               // 110592

template<int MODE, bool W32, bool W16>
__global__ __launch_bounds__(256, 2) void gemm_h(
    const __half* __restrict__ A, const __half* __restrict__ B,
    float* __restrict__ C, __half* __restrict__ C16,
    int N, int K, int lda, int ldb, int ntx, int ntiles,
    const float* __restrict__ bias, const float* __restrict__ resid)
{
    extern __shared__ char smraw[];
    const int tid = threadIdx.x;
    const int wid = tid >> 5, lane = tid & 31;
    const int gid = lane >> 2, t4 = lane & 3;
    const int wm = (wid >> 2) * 64, wn = (wid & 3) * 32;
    const int NC = K >> 6;                      // K chunks of 64
    uint32_t sbase = smem_u32(smraw);

    const uint32_t aoff = (uint32_t)((wm + (lane & 15)) * PITCH_H + ((lane >> 4) << 3)) * 2;
    const uint32_t boff = 128 * PITCH_H * 2 +
        (uint32_t)((wn + ((lane >> 4) << 3) + (lane & 7)) * PITCH_H + (((lane >> 3) & 1) << 3)) * 2;

    for (int tile = blockIdx.x; tile < ntiles; tile += gridDim.x) {
        const int row0 = (tile / ntx) * 128, col0 = (tile % ntx) * 128;

        auto load_chunk = [&](int c, int s) {
            uint32_t As = sbase + (uint32_t)s * STG_BYTES;
            uint32_t Bs = As + 128 * PITCH_H * 2;
            int k0 = c * 64;
            #pragma unroll
            for (int i = 0; i < 4; i++) {
                int idx = tid + 256 * i;
                int r = idx >> 3, c8 = (idx & 7) * 8;
                cp16(As + (uint32_t)(r * PITCH_H + c8) * 2,
                     A + (size_t)(row0 + r) * lda + k0 + c8);
            }
            #pragma unroll
            for (int i = 0; i < 4; i++) {
                int idx = tid + 256 * i;
                int r = idx >> 3, c8 = (idx & 7) * 8;
                int brow = col0 + r;
                const __half* src = B + (size_t)(brow < N ? brow : 0) * ldb + k0 + c8;
                cp16z(Bs + (uint32_t)(r * PITCH_H + c8) * 2, src, brow < N ? 16 : 0);
            }
        };

        float acc[4][4][4];
        #pragma unroll
        for (int i = 0; i < 4; i++)
            #pragma unroll
            for (int j = 0; j < 4; j++)
                #pragma unroll
                for (int q = 0; q < 4; q++) acc[i][j][q] = 0.f;

        #pragma unroll
        for (int c = 0; c < 2; c++) {
            if (c < NC) load_chunk(c, c);
            CP_COMMIT();
        }

        for (int c = 0; c < NC; c++) {
            if (c + 2 < NC) load_chunk(c + 2, (c + 2) % 3);
            CP_COMMIT();
            CP_WAIT2();
            __syncthreads();

            uint32_t stage = sbase + (uint32_t)(c % 3) * STG_BYTES;
            #pragma unroll
            for (int k16 = 0; k16 < 4; k16++) {
                uint32_t kb = (uint32_t)(k16 * 16) * 2;
                uint32_t af[4][4], bf[4][2];
                #pragma unroll
                for (int mt = 0; mt < 4; mt++)
                    lm4(af[mt][0], af[mt][1], af[mt][2], af[mt][3],
                        stage + aoff + kb + (uint32_t)(mt * 16 * PITCH_H) * 2);
                #pragma unroll
                for (int np = 0; np < 2; np++)
                    lm4(bf[2*np][0], bf[2*np][1], bf[2*np+1][0], bf[2*np+1][1],
                        stage + boff + kb + (uint32_t)(np * 16 * PITCH_H) * 2);
                #pragma unroll
                for (int mt = 0; mt < 4; mt++)
                    #pragma unroll
                    for (int nt = 0; nt < 4; nt++)
                        mma_f16(acc[mt][nt], af[mt], bf[nt]);
            }
            __syncthreads();
        }

        // ---- epilogue --------------------------------------------------
        #pragma unroll
        for (int mt = 0; mt < 4; mt++) {
            #pragma unroll
            for (int r2 = 0; r2 < 2; r2++) {
                int m = row0 + wm + mt * 16 + gid + r2 * 8;
                #pragma unroll
                for (int nt = 0; nt < 4; nt++) {
                    int n = col0 + wn + nt * 8 + 2 * t4;
                    if (n < N) {
                        float v0 = acc[mt][nt][r2 * 2];
                        float v1 = acc[mt][nt][r2 * 2 + 1];
                        if (MODE == 1 || MODE == 3 || MODE == 4) {
                            v0 += bias[n]; v1 += bias[n + 1];
                        }
                        if (MODE == 1) {
                            v0 = (v0 > 20.f) ? v0 : log1pf(expf(v0));
                            v1 = (v1 > 20.f) ? v1 : log1pf(expf(v1));
                        }
                        if (MODE == 3) {
                            const float kq = 0.70710678118654752f;
                            v0 = 0.5f * v0 * (1.f + erff(v0 * kq));
                            v1 = 0.5f * v1 * (1.f + erff(v1 * kq));
                        }
                        if (MODE == 2 || MODE == 4) {
                            const float* rp = resid + (size_t)m * N + n;
                            v0 += rp[0]; v1 += rp[1];
                        }
                        if (W32)
                            *(float2*)(C + (size_t)m * N + n) = make_float2(v0, v1);
                        if (W16)
                            *(__half2*)(C16 + (size_t)m * N + n) = __floats2half2_rn(v0, v1);
                    }
                }
            }
        }
    }
}

// ======================= weight conversion ==================================
struct CvtArgs {
    const float* src[6];
    __half* dst[6];
    int off[7];
};
__global__ __launch_bounds__(256) void cvt_kernel(CvtArgs a) {
    int i = blockIdx.x * blockDim.x + threadIdx.x;
    if (i >= a.off[6]) return;
    int s = 0;
    #pragma unroll
    for (int k = 1; k < 6; k++) if (i >= a.off[k]) s = k;
    int j = i - a.off[s];
    float4 v = ((const float4*)a.src[s])[j];
    __half2* d = (__half2*)a.dst[s];
    d[2 * j]     = __floats2half2_rn(v.x, v.y);
    d[2 * j + 1] = __floats2half2_rn(v.z, v.w);
}

// ======================= LayerNorm (f16 out) ================================
__global__ __launch_bounds__(256) void ln_kernel(
    const float* __restrict__ in, __half* __restrict__ out,
    const float* __restrict__ g, const float* __restrict__ b)
{
    int row = blockIdx.x;
    const float* x = in + (size_t)row * DIM;
    float4 v = *(const float4*)(x + threadIdx.x * 4);
    float s  = v.x + v.y + v.z + v.w;
    float sq = v.x*v.x + v.y*v.y + v.z*v.z + v.w*v.w;
    #pragma unroll
    for (int o = 16; o; o >>= 1) {
        s  += __shfl_xor_sync(0xffffffffu, s,  o);
        sq += __shfl_xor_sync(0xffffffffu, sq, o);
    }
    __shared__ float ss[8], sqq[8];
    int w = threadIdx.x >> 5;
    if ((threadIdx.x & 31) == 0) { ss[w] = s; sqq[w] = sq; }
    __syncthreads();
    s = 0.f; sq = 0.f;
    #pragma unroll
    for (int i = 0; i < 8; i++) { s += ss[i]; sq += sqq[i]; }
    float mu = s * (1.0f / DIM);
    float var = sq * (1.0f / DIM) - mu * mu;
    float rs = rsqrtf(var + LN_EPS);
    float4 gg = *(const float4*)(g + threadIdx.x * 4);
    float4 bb = *(const float4*)(b + threadIdx.x * 4);
    __half2 p0 = __floats2half2_rn((v.x - mu) * rs * gg.x + bb.x,
                                   (v.y - mu) * rs * gg.y + bb.y);
    __half2 p1 = __floats2half2_rn((v.z - mu) * rs * gg.z + bb.z,
                                   (v.w - mu) * rs * gg.w + bb.w);
    __half2* o2 = (__half2*)(out + (size_t)row * DIM);
    o2[threadIdx.x * 2] = p0;
    o2[threadIdx.x * 2 + 1] = p1;
}

// ---------------- depthwise conv + SiLU (vectorized: 2 channels/thread) -----
__device__ __forceinline__ float silu(float v) { return v / (1.0f + __expf(-v)); }

__global__ __launch_bounds__(256) void conv_silu_kernel(
    const __half* __restrict__ xz,
    const float* __restrict__ wx, const float* __restrict__ bx,
    const float* __restrict__ wz, const float* __restrict__ bz,
    __half* __restrict__ u16, __half* __restrict__ y16)
{
    int idx = blockIdx.x * blockDim.x + threadIdx.x;   // NTOK*HALF/2 threads
    int d2 = idx & (HALF / 2 - 1);
    int d = d2 * 2;
    int token = idx >> 9;
    int b = token >> 11;
    int l = token & (SEQ - 1);

    float4 wxa = ((const float4*)wx)[d];
    float4 wxb = ((const float4*)wx)[d + 1];
    float4 wza = ((const float4*)wz)[d];
    float4 wzb = ((const float4*)wz)[d + 1];
    float ax0 = bx[d], ax1 = bx[d + 1];
    float az0 = bz[d], az1 = bz[d + 1];

    const __half* base = xz + (size_t)(b * SEQ) * DINNER + d;
    #pragma unroll
    for (int k = 0; k < DCONV; k++) {
        int lp = l - 1 + k;
        if (lp >= 0 && lp < SEQ) {
            float2 xv = __half22float2(*(const __half2*)(base + (size_t)lp * DINNER));
            float2 zv = __half22float2(*(const __half2*)(base + (size_t)lp * DINNER + HALF));
            float wxk0 = (&wxa.x)[k], wxk1 = (&wxb.x)[k];
            float wzk0 = (&wza.x)[k], wzk1 = (&wzb.x)[k];
            ax0 += xv.x * wxk0; ax1 += xv.y * wxk1;
            az0 += zv.x * wzk0; az1 += zv.y * wzk1;
        }
    }
    *(__half2*)(u16 + (size_t)token * HALF + d) =
        __floats2half2_rn(silu(ax0), silu(ax1));
    *(__half2*)(y16 + (size_t)token * DINNER + HALF + d) =
        __floats2half2_rn(silu(az0), silu(az1));
}

// ---------------- selective scan: 8 lanes/channel, 2 states/lane ------------
// Warp = 4 channels. B/C loaded as float2. 3-level shfl tree within 8 lanes.
__global__ __launch_bounds__(64) void scan_kernel(
    const float* __restrict__ delta, const __half* __restrict__ u,
    const float* __restrict__ xdbl, const float* __restrict__ A_log,
    const float* __restrict__ Dp, __half* __restrict__ y)
{
    int gt = blockIdx.x * 64 + threadIdx.x;   // BSZ*HALF*8 threads
    int c = gt >> 3;                           // channel 0..2047
    int ln = gt & 7;                           // 8 lanes per channel
    int b = c >> 10;
    int d = c & (HALF - 1);
    int n0 = ln * 2;                           // states n0, n0+1

    float2 al = *(const float2*)(A_log + d * DSTATE + n0);
    float a0 = -expf(al.x), a1 = -expf(al.y);
    float Dd = Dp[d];
    float h0 = 0.f, h1 = 0.f;

    const float*  dptr = delta + (size_t)b * SEQ * HALF + d;
    const __half* uptr = u     + (size_t)b * SEQ * HALF + d;
    const float*  bptr = xdbl  + (size_t)b * SEQ * 96 + DTRANK + n0;
    const float*  cptr = xdbl  + (size_t)b * SEQ * 96 + DTRANK + DSTATE + n0;
    __half* yptr = y + (size_t)b * SEQ * DINNER + d;

    float dl[8], uv[8];
    float2 Bv[8], Cv[8];
    #pragma unroll
    for (int j = 0; j < 8; j++) {
        dl[j] = dptr[j * HALF]; uv[j] = __half2float(uptr[j * HALF]);
        Bv[j] = *(const float2*)(bptr + j * 96);
        Cv[j] = *(const float2*)(cptr + j * 96);
    }

    for (int t = 0; t < SEQ; t += 8) {
        float nd[8], nu[8];
        float2 nB[8], nC[8];
        #pragma unroll
        for (int j = 0; j < 8; j++) {
            int tp = t + 8 + j; tp = (tp < SEQ) ? tp : SEQ - 1;
            nd[j] = dptr[tp * HALF]; nu[j] = __half2float(uptr[tp * HALF]);
            nB[j] = *(const float2*)(bptr + tp * 96);
            nC[j] = *(const float2*)(cptr + tp * 96);
        }

        float p[8];
        #pragma unroll
        for (int j = 0; j < 8; j++) {
            float e0 = __expf(dl[j] * a0);
            float e1 = __expf(dl[j] * a1);
            float du = dl[j] * uv[j];
            h0 = e0 * h0 + du * Bv[j].x;
            h1 = e1 * h1 + du * Bv[j].y;
            p[j] = h0 * Cv[j].x + h1 * Cv[j].y;
        }

        // 3-level tree within each 8-lane group (8 interleaved chains)
        #pragma unroll
        for (int o = 4; o; o >>= 1) {
            #pragma unroll
            for (int j = 0; j < 8; j++)
                p[j] += __shfl_xor_sync(0xffffffffu, p[j], o);
        }

        if (ln == 0) {
            #pragma unroll
            for (int j = 0; j < 8; j++)
                yptr[(size_t)(t + j) * DINNER] = __float2half(p[j] + uv[j] * Dd);
        }
        #pragma unroll
        for (int j = 0; j < 8; j++) {
            dl[j] = nd[j]; uv[j] = nu[j]; Bv[j] = nB[j]; Cv[j] = nC[j];
        }
    }
}

// ======================= launch =============================================
static inline int pgrid(int ntiles) { return ntiles < NPERSIST ? ntiles : NPERSIST; }

extern "C" void kernel_launch(void* const* d_in, const int* in_sizes, int n_in,
                              void* d_out, int out_size)
{
    const float* x         = (const float*)d_in[0];
    const float* ln1_g     = (const float*)d_in[1];
    const float* ln1_b     = (const float*)d_in[2];
    const float* in_proj_w = (const float*)d_in[3];
    const float* conv_x_w  = (const float*)d_in[4];
    const float* conv_x_b  = (const float*)d_in[5];
    const float* conv_z_w  = (const float*)d_in[6];
    const float* conv_z_b  = (const float*)d_in[7];
    const float* x_proj_w  = (const float*)d_in[8];
    const float* dt_proj_w = (const float*)d_in[9];
    const float* dt_proj_b = (const float*)d_in[10];
    const float* A_log     = (const float*)d_in[11];
    const float* Dp        = (const float*)d_in[12];
    const float* out_proj_w= (const float*)d_in[13];
    const float* ln2_g     = (const float*)d_in[14];
    const float* ln2_b     = (const float*)d_in[15];
    const float* mlp_w1    = (const float*)d_in[16];
    const float* mlp_b1    = (const float*)d_in[17];
    const float* mlp_w2    = (const float*)d_in[18];
    const float* mlp_b2    = (const float*)d_in[19];
    float* out = (float*)d_out;

    float *xdbl, *delta, *res1;
    cudaGetSymbolAddress((void**)&xdbl, g_xdbl);
    cudaGetSymbolAddress((void**)&delta,g_delta);
    cudaGetSymbolAddress((void**)&res1, g_res1);

    __half *hln1, *hxz, *hu, *hxdbl, *hy, *hln2, *hmlp;
    __half *win, *wxp, *wdt, *wout, *wm1, *wm2;
    cudaGetSymbolAddress((void**)&hln1, h_ln1);
    cudaGetSymbolAddress((void**)&hxz,  h_xz);
    cudaGetSymbolAddress((void**)&hu,   h_u);
    cudaGetSymbolAddress((void**)&hxdbl,h_xdbl);
    cudaGetSymbolAddress((void**)&hy,   h_y);
    cudaGetSymbolAddress((void**)&hln2, h_ln2);
    cudaGetSymbolAddress((void**)&hmlp, h_mlp);
    cudaGetSymbolAddress((void**)&win,  w16_in);
    cudaGetSymbolAddress((void**)&wxp,  w16_xp);
    cudaGetSymbolAddress((void**)&wdt,  w16_dt);
    cudaGetSymbolAddress((void**)&wout, w16_out);
    cudaGetSymbolAddress((void**)&wm1,  w16_m1);
    cudaGetSymbolAddress((void**)&wm2,  w16_m2);

    cudaFuncSetAttribute(gemm_h<0,false,true>, cudaFuncAttributeMaxDynamicSharedMemorySize, GEMM_SMEM);
    cudaFuncSetAttribute(gemm_h<0,true,true>,  cudaFuncAttributeMaxDynamicSharedMemorySize, GEMM_SMEM);
    cudaFuncSetAttribute(gemm_h<1,true,false>, cudaFuncAttributeMaxDynamicSharedMemorySize, GEMM_SMEM);
    cudaFuncSetAttribute(gemm_h<2,true,false>, cudaFuncAttributeMaxDynamicSharedMemorySize, GEMM_SMEM);
    cudaFuncSetAttribute(gemm_h<3,false,true>, cudaFuncAttributeMaxDynamicSharedMemorySize, GEMM_SMEM);
    cudaFuncSetAttribute(gemm_h<4,true,false>, cudaFuncAttributeMaxDynamicSharedMemorySize, GEMM_SMEM);

    // 0. convert weights to f16
    CvtArgs ca;
    ca.src[0] = in_proj_w;  ca.dst[0] = win;  int n0 = DINNER * DIM / 4;
    ca.src[1] = x_proj_w;   ca.dst[1] = wxp;  int n1 = 96 * HALF / 4;
    ca.src[2] = dt_proj_w;  ca.dst[2] = wdt;  int n2 = HALF * DTRANK / 4;
    ca.src[3] = out_proj_w; ca.dst[3] = wout; int n3 = DIM * DINNER / 4;
    ca.src[4] = mlp_w1;     ca.dst[4] = wm1;  int n4 = MLPD * DIM / 4;
    ca.src[5] = mlp_w2;     ca.dst[5] = wm2;  int n5 = DIM * MLPD / 4;
    ca.off[0] = 0;
    ca.off[1] = n0; ca.off[2] = n0+n1; ca.off[3] = n0+n1+n2;
    ca.off[4] = n0+n1+n2+n3; ca.off[5] = n0+n1+n2+n3+n4; ca.off[6] = n0+n1+n2+n3+n4+n5;
    cvt_kernel<<<(ca.off[6] + 255) / 256, 256>>>(ca);

    // 1. LN1 -> f16
    ln_kernel<<<NTOK, 256>>>(x, hln1, ln1_g, ln1_b);
    // 2. in_proj -> xz f16 (512 tiles)
    gemm_h<0,false,true><<<pgrid(512), 256, GEMM_SMEM>>>(
        hln1, win, nullptr, hxz, DINNER, DIM, DIM, DIM, 16, 512, nullptr, nullptr);
    // 3. conv + silu (2 channels/thread)
    conv_silu_kernel<<<(NTOK*HALF/2)/256, 256>>>(hxz, conv_x_w, conv_x_b,
                                                 conv_z_w, conv_z_b, hu, hy);
    // 4. x_proj (32 tiles)
    gemm_h<0,true,true><<<pgrid(32), 256, GEMM_SMEM>>>(
        hu, wxp, xdbl, hxdbl, 96, HALF, HALF, HALF, 1, 32, nullptr, nullptr);
    // 5. dt_proj + softplus -> delta f32 (256 tiles)
    gemm_h<1,true,false><<<pgrid(256), 256, GEMM_SMEM>>>(
        hxdbl, wdt, delta, nullptr, HALF, DTRANK, 96, DTRANK, 8, 256,
        dt_proj_b, nullptr);
    // 6. selective scan -> h_y left half (8 lanes/channel, 64-thr blocks)
    scan_kernel<<<(BSZ*HALF*8)/64, 64>>>(delta, hu, xdbl, A_log, Dp, hy);
    // 7. out_proj + residual (256 tiles)
    gemm_h<2,true,false><<<pgrid(256), 256, GEMM_SMEM>>>(
        hy, wout, res1, nullptr, DIM, DINNER, DINNER, DINNER, 8, 256,
        nullptr, x);
    // 8. LN2 -> f16
    ln_kernel<<<NTOK, 256>>>(res1, hln2, ln2_g, ln2_b);
    // 9. mlp1 + gelu -> f16 (1024 tiles)
    gemm_h<3,false,true><<<pgrid(1024), 256, GEMM_SMEM>>>(
        hln2, wm1, nullptr, hmlp, MLPD, DIM, DIM, DIM, 32, 1024,
        mlp_b1, nullptr);
    // 10. mlp2 + bias + residual -> out (256 tiles)
    gemm_h<4,true,false><<<pgrid(256), 256, GEMM_SMEM>>>(
        hmlp, wm2, out, nullptr, DIM, MLPD, MLPD, MLPD, 8, 256,
        mlp_b2, res1);
}